// round 6
// baseline (speedup 1.0000x reference)
#include <cuda_runtime.h>
#include <cuda_bf16.h>
#include <cstdint>

#define BB 4
#define NN 4096
#define FF 128
#define NIT 256           // 4096 / 16 j-tiles

// ---------------- scratch (no allocations allowed) ----------------
__device__ uint4  g_WhTh[(size_t)BB * FF * NN / 8];   // WhT hi bf16 [b][f][j], 4MB
__device__ uint4  g_WhTl[(size_t)BB * FF * NN / 8];   // WhT lo bf16            4MB
__device__ float  g_si[BB * NN];
__device__ float2 g_uv[BB * NN];                      // {e^{sj}, e^{0.2 sj}}

// ---------------- helpers ----------------
__device__ __forceinline__ unsigned long long pack2(float lo, float hi) {
    unsigned long long r; asm("mov.b64 %0, {%1, %2};" : "=l"(r) : "f"(lo), "f"(hi)); return r;
}
__device__ __forceinline__ unsigned long long bcast2(float v) {
    unsigned long long r; asm("mov.b64 %0, {%1, %1};" : "=l"(r) : "f"(v)); return r;
}
__device__ __forceinline__ void fma2(unsigned long long& d, unsigned long long a, unsigned long long b) {
    asm("fma.rn.f32x2 %0, %1, %2, %0;" : "+l"(d) : "l"(a), "l"(b));
}
__device__ __forceinline__ float2 unpack2(unsigned long long v) {
    float2 f; asm("mov.b64 {%0, %1}, %2;" : "=f"(f.x), "=f"(f.y) : "l"(v)); return f;
}
// pack two floats -> bf16x2 RNE (first arg in low half)
__device__ __forceinline__ uint32_t pkbf2(float lo, float hi) {
    uint32_t r; asm("cvt.rn.bf16x2.f32 %0, %2, %1;" : "=r"(r) : "f"(lo), "f"(hi)); return r;
}
__device__ __forceinline__ void mma_bf16(float* c, uint32_t a0, uint32_t a1,
                                         uint32_t a2, uint32_t a3,
                                         uint32_t b0, uint32_t b1) {
    asm volatile(
        "mma.sync.aligned.m16n8k16.row.col.f32.bf16.bf16.f32 "
        "{%0,%1,%2,%3}, {%4,%5,%6,%7}, {%8,%9}, {%0,%1,%2,%3};"
        : "+f"(c[0]), "+f"(c[1]), "+f"(c[2]), "+f"(c[3])
        : "r"(a0), "r"(a1), "r"(a2), "r"(a3), "r"(b0), "r"(b1));
}

// =====================================================================
// Kernel A: Wh = h @ W ; 32 rows x 128 f per CTA, 256 threads.
// Epilogue: bf16 hi/lo split, store WhT[b][f][j].
// =====================================================================
__global__ void __launch_bounds__(256) k_wh(const float* __restrict__ h,
                                            const float* __restrict__ W) {
    const int b = blockIdx.y;
    const int i0 = blockIdx.x * 32;

    __shared__ float hsT[32][40];    // [k][r], padded (row = 160B, 16B aligned)
    __shared__ float Ws[32][128];    // [k][f]

    const int tid = threadIdx.x;
    const int fgrp = tid & 31, rgrp = tid >> 5;
    const int rbase = rgrp * 4, fbase = fgrp * 4;

    unsigned long long acc[4][2];
#pragma unroll
    for (int r = 0; r < 4; r++) { acc[r][0] = 0ULL; acc[r][1] = 0ULL; }

    for (int k0 = 0; k0 < FF; k0 += 32) {
        __syncthreads();
        {   // h tile: 32 rows x 32 k (one float4 per thread), transposed store
            int r = tid >> 3, kq = tid & 7;
            float4 v = *(const float4*)(h + ((size_t)(b * NN + i0 + r)) * FF + k0 + kq * 4);
            hsT[kq * 4 + 0][r] = v.x;
            hsT[kq * 4 + 1][r] = v.y;
            hsT[kq * 4 + 2][r] = v.z;
            hsT[kq * 4 + 3][r] = v.w;
        }
#pragma unroll
        for (int q = 0; q < 4; q++) {   // W chunk: 32 k x 128 f
            int idx = tid + 256 * q;
            int kk = idx >> 5, fq = idx & 31;
            *(float4*)&Ws[kk][fq * 4] = *(const float4*)(W + (size_t)(k0 + kk) * FF + fq * 4);
        }
        __syncthreads();

#pragma unroll 8
        for (int kk = 0; kk < 32; kk++) {
            float4 hr = *(float4*)&hsT[kk][rbase];
            float4 wf = *(float4*)&Ws[kk][fbase];
            unsigned long long w01 = pack2(wf.x, wf.y);
            unsigned long long w23 = pack2(wf.z, wf.w);
            float hv[4] = {hr.x, hr.y, hr.z, hr.w};
#pragma unroll
            for (int r = 0; r < 4; r++) {
                unsigned long long hb = bcast2(hv[r]);
                fma2(acc[r][0], hb, w01);
                fma2(acc[r][1], hb, w23);
            }
        }
    }

    float va[4][4];
#pragma unroll
    for (int r = 0; r < 4; r++) {
        float2 t0 = unpack2(acc[r][0]);
        float2 t1 = unpack2(acc[r][1]);
        va[r][0] = t0.x; va[r][1] = t0.y; va[r][2] = t1.x; va[r][3] = t1.y;
    }

#pragma unroll
    for (int f = 0; f < 4; f++) {
        uint32_t h01 = pkbf2(va[0][f], va[1][f]);
        uint32_t h23 = pkbf2(va[2][f], va[3][f]);
        float r0h = __uint_as_float(h01 << 16);
        float r1h = __uint_as_float(h01 & 0xFFFF0000u);
        float r2h = __uint_as_float(h23 << 16);
        float r3h = __uint_as_float(h23 & 0xFFFF0000u);
        uint32_t l01 = pkbf2(va[0][f] - r0h, va[1][f] - r1h);
        uint32_t l23 = pkbf2(va[2][f] - r2h, va[3][f] - r3h);
        size_t idx = ((size_t)(b * FF) + fbase + f) * NN + i0 + rbase;
        ((uint2*)g_WhTh)[idx >> 2] = make_uint2(h01, h23);
        ((uint2*)g_WhTl)[idx >> 2] = make_uint2(l01, l23);
    }
}

// =====================================================================
// Kernel B: si, (u=e^{sj}, v=e^{0.2 sj}) from bf16-pair WhT
// =====================================================================
__global__ void __launch_bounds__(256) k_sisj(const float* __restrict__ a) {
    __shared__ float as[256];
    as[threadIdx.x] = a[threadIdx.x];
    __syncthreads();

    int idx = blockIdx.x * 256 + threadIdx.x;
    int b = idx >> 12;
    int i = idx & (NN - 1);

    const __nv_bfloat16* ph = (const __nv_bfloat16*)g_WhTh + (size_t)b * FF * NN + i;
    const __nv_bfloat16* pl = (const __nv_bfloat16*)g_WhTl + (size_t)b * FF * NN + i;
    float si = 0.f, sj = 0.f;
#pragma unroll 16
    for (int f = 0; f < FF; f++) {
        float w = __bfloat162float(ph[(size_t)f * NN]) + __bfloat162float(pl[(size_t)f * NN]);
        si += w * as[f];
        sj += w * as[f + FF];
    }
    g_si[idx] = si;
    g_uv[idx] = make_float2(__expf(sj), __expf(0.2f * sj));
}

// =====================================================================
// Kernel C: fused masked-softmax + P @ Wh via mma.sync bf16 (3-term) + ELU
// A-fragment gen (tile t+1) decoupled from mma burst (tile t) so the
// tensor pipe never waits on P generation.
// =====================================================================
__global__ void __launch_bounds__(256, 1) k_attn(const int* __restrict__ adj,
                                                 float* __restrict__ out) {
    __shared__ float2 uvS[NN];          // 32 KB
    __shared__ uint4  stg4[1024];       // 16 KB: 2 stages x 2 arrays x 128f x 32B
    char* stg = (char*)stg4;

    const int tid = threadIdx.x;
    const int lane = tid & 31, w = tid >> 5;
    const int c = lane & 3, fq = lane >> 2;
    const int b = blockIdx.y;
    const int i0 = blockIdx.x * 128;

#pragma unroll
    for (int k = 0; k < 16; k++) {
        int idx = tid + 256 * k;
        uvS[idx] = g_uv[b * NN + idx];
    }

    const int r0 = i0 + w * 16 + fq;
    const int r1 = r0 + 8;
    const float si0 = g_si[b * NN + r0];
    const float si1 = g_si[b * NN + r1];
    const float c10 = __expf(si0), c20 = __expf(0.2f * si0), th0 = __expf(-si0);
    const float c11 = __expf(si1), c21 = __expf(0.2f * si1), th1 = __expf(-si1);

    const int2* a00 = (const int2*)(adj + ((size_t)(b * NN + r0)) * NN + 2 * c);
    const int2* a10 = (const int2*)(adj + ((size_t)(b * NN + r1)) * NN + 2 * c);

    // staging role
    const int arr = tid >> 7;
    const int f = tid & 127;
    const int kf = f & 7;
    const uint4* src = (arr ? g_WhTl : g_WhTh) + (size_t)(b * FF + f) * (NN / 8);
    uint32_t* dst0 = (uint32_t*)(stg + arr * 4096 + f * 32);

    // consumer B addressing
    const int swz0 = ((c ^ fq) << 2);
    const int swz1 = (((c + 4) ^ fq) << 2);
    const char* bb = stg + fq * 32;
    const float2* uvp = uvS + 2 * c;

    float acc[16][4];
#pragma unroll
    for (int nt = 0; nt < 16; nt++)
#pragma unroll
        for (int k = 0; k < 4; k++) acc[nt][k] = 0.f;
    float z0 = 0.f, z1 = 0.f;

    uint32_t af0h[4], af0l[4], af1h[4], af1l[4];

    // prologue prefetch
    uint4 cb0 = src[0], cb1 = src[1];
    int2 A00 = __ldcs(a00), A01 = __ldcs(a00 + 4);
    int2 A10 = __ldcs(a10), A11 = __ldcs(a10 + 4);

    // A-fragment generation for tile tc (register/uvS only; prefetches adj tc+1)
    auto genA = [&](int tc, uint32_t* fh, uint32_t* fl) {
        const int J = tc * 16;
        float4 uvA = *(const float4*)(uvp + J);
        float4 uvB = *(const float4*)(uvp + J + 8);
        float p00 = A00.x > 0 ? (uvA.x > th0 ? c10 * uvA.x : c20 * uvA.y) : 0.f;
        float p01 = A00.y > 0 ? (uvA.z > th0 ? c10 * uvA.z : c20 * uvA.w) : 0.f;
        float p08 = A01.x > 0 ? (uvB.x > th0 ? c10 * uvB.x : c20 * uvB.y) : 0.f;
        float p09 = A01.y > 0 ? (uvB.z > th0 ? c10 * uvB.z : c20 * uvB.w) : 0.f;
        float p10 = A10.x > 0 ? (uvA.x > th1 ? c11 * uvA.x : c21 * uvA.y) : 0.f;
        float p11 = A10.y > 0 ? (uvA.z > th1 ? c11 * uvA.z : c21 * uvA.w) : 0.f;
        float p18 = A11.x > 0 ? (uvB.x > th1 ? c11 * uvB.x : c21 * uvB.y) : 0.f;
        float p19 = A11.y > 0 ? (uvB.z > th1 ? c11 * uvB.z : c21 * uvB.w) : 0.f;
        z0 += (p00 + p01) + (p08 + p09);
        z1 += (p10 + p11) + (p18 + p19);
        if (tc + 1 < NIT) {
            int o = (tc + 1) * 8;
            A00 = __ldcs(a00 + o); A01 = __ldcs(a00 + o + 4);
            A10 = __ldcs(a10 + o); A11 = __ldcs(a10 + o + 4);
        }
        uint32_t h0 = pkbf2(p00, p01), h1 = pkbf2(p10, p11);
        uint32_t h2 = pkbf2(p08, p09), h3 = pkbf2(p18, p19);
        fh[0] = h0; fh[1] = h1; fh[2] = h2; fh[3] = h3;
        fl[0] = pkbf2(p00 - __uint_as_float(h0 << 16), p01 - __uint_as_float(h0 & 0xFFFF0000u));
        fl[1] = pkbf2(p10 - __uint_as_float(h1 << 16), p11 - __uint_as_float(h1 & 0xFFFF0000u));
        fl[2] = pkbf2(p08 - __uint_as_float(h2 << 16), p09 - __uint_as_float(h2 & 0xFFFF0000u));
        fl[3] = pkbf2(p18 - __uint_as_float(h3 << 16), p19 - __uint_as_float(h3 & 0xFFFF0000u));
    };

    auto mmaL = [&](const char* sbb, const uint32_t* fh, const uint32_t* fl) {
#pragma unroll
        for (int nt = 0; nt < 16; nt++) {
            const char* pb = sbb + nt * 256;
            uint32_t bh0 = *(const uint32_t*)(pb + swz0);
            uint32_t bh1 = *(const uint32_t*)(pb + swz1);
            uint32_t bl0 = *(const uint32_t*)(pb + 4096 + swz0);
            uint32_t bl1 = *(const uint32_t*)(pb + 4096 + swz1);
            mma_bf16(acc[nt], fh[0], fh[1], fh[2], fh[3], bh0, bh1);
            mma_bf16(acc[nt], fh[0], fh[1], fh[2], fh[3], bl0, bl1);
            mma_bf16(acc[nt], fl[0], fl[1], fl[2], fl[3], bh0, bh1);
        }
    };

    __syncthreads();      // uvS visible
    genA(0, af0h, af0l);

#pragma unroll 1
    for (int t = 0; t < NIT; t += 2) {
        // even half: stage t -> buf0, mma tile t-1 (buf1, af1), gen tile t+1 -> af1
        __syncthreads();
        {
            uint32_t* d = dst0;
            d[0 ^ kf] = cb0.x; d[1 ^ kf] = cb0.y; d[2 ^ kf] = cb0.z; d[3 ^ kf] = cb0.w;
            d[4 ^ kf] = cb1.x; d[5 ^ kf] = cb1.y; d[6 ^ kf] = cb1.z; d[7 ^ kf] = cb1.w;
        }
        cb0 = src[2 * t + 2]; cb1 = src[2 * t + 3];
        if (t > 0) mmaL(bb + 8192, af1h, af1l);
        genA(t + 1, af1h, af1l);

        // odd half: stage t+1 -> buf1, mma tile t (buf0, af0), gen tile t+2 -> af0
        __syncthreads();
        {
            uint32_t* d = dst0 + 2048;
            d[0 ^ kf] = cb0.x; d[1 ^ kf] = cb0.y; d[2 ^ kf] = cb0.z; d[3 ^ kf] = cb0.w;
            d[4 ^ kf] = cb1.x; d[5 ^ kf] = cb1.y; d[6 ^ kf] = cb1.z; d[7 ^ kf] = cb1.w;
        }
        if (t + 2 < NIT) { cb0 = src[2 * t + 4]; cb1 = src[2 * t + 5]; }
        mmaL(bb, af0h, af0l);
        if (t + 2 < NIT) genA(t + 2, af0h, af0l);
    }
    __syncthreads();
    mmaL(bb + 8192, af1h, af1l);    // tile NIT-1

    // Z reduction over the 4 lanes sharing a row
    z0 += __shfl_xor_sync(0xFFFFFFFFu, z0, 1);
    z0 += __shfl_xor_sync(0xFFFFFFFFu, z0, 2);
    z1 += __shfl_xor_sync(0xFFFFFFFFu, z1, 1);
    z1 += __shfl_xor_sync(0xFFFFFFFFu, z1, 2);
    const float iz0 = 1.0f / z0;
    const float iz1 = 1.0f / z1;

    float* o0 = out + ((size_t)(b * NN + r0)) * FF + 2 * c;
    float* o1 = out + ((size_t)(b * NN + r1)) * FF + 2 * c;
#pragma unroll
    for (int nt = 0; nt < 16; nt++) {
        float x0 = acc[nt][0] * iz0, x1 = acc[nt][1] * iz0;
        float y0 = acc[nt][2] * iz1, y1 = acc[nt][3] * iz1;
        x0 = x0 > 0.f ? x0 : (__expf(x0) - 1.0f);
        x1 = x1 > 0.f ? x1 : (__expf(x1) - 1.0f);
        y0 = y0 > 0.f ? y0 : (__expf(y0) - 1.0f);
        y1 = y1 > 0.f ? y1 : (__expf(y1) - 1.0f);
        *(float2*)(o0 + nt * 8) = make_float2(x0, x1);
        *(float2*)(o1 + nt * 8) = make_float2(y0, y1);
    }
}

// =====================================================================
extern "C" void kernel_launch(void* const* d_in, const int* in_sizes, int n_in,
                              void* d_out, int out_size) {
    const float* h   = (const float*)d_in[0];
    const int*   adj = (const int*)d_in[1];
    const float* W   = (const float*)d_in[2];
    const float* a   = (const float*)d_in[3];
    float* out = (float*)d_out;

    k_wh<<<dim3(NN / 32, BB), 256>>>(h, W);
    k_sisj<<<BB * NN / 256, 256>>>(a);
    k_attn<<<dim3(NN / 128, BB), 256>>>(adj, out);
}

// round 7
// speedup vs baseline: 1.8946x; 1.8946x over previous
#include <cuda_runtime.h>
#include <cuda_fp16.h>
#include <cstdint>

#define BB 4
#define NN 4096
#define FF 128
#define NIT 256           // 4096 / 16 j-tiles

// ---------------- scratch (no allocations allowed) ----------------
__device__ uint4  g_Wh[(size_t)BB * FF * NN / 8];    // WhT fp16 [b][f][j], 4MB
__device__ float  g_si[BB * NN];
__device__ float2 g_uv[BB * NN];                     // {e^{sj}, e^{0.2 sj}}

// ---------------- helpers ----------------
__device__ __forceinline__ unsigned long long pack2(float lo, float hi) {
    unsigned long long r; asm("mov.b64 %0, {%1, %2};" : "=l"(r) : "f"(lo), "f"(hi)); return r;
}
__device__ __forceinline__ unsigned long long bcast2(float v) {
    unsigned long long r; asm("mov.b64 %0, {%1, %1};" : "=l"(r) : "f"(v)); return r;
}
__device__ __forceinline__ void fma2(unsigned long long& d, unsigned long long a, unsigned long long b) {
    asm("fma.rn.f32x2 %0, %1, %2, %0;" : "+l"(d) : "l"(a), "l"(b));
}
__device__ __forceinline__ float2 unpack2(unsigned long long v) {
    float2 f; asm("mov.b64 {%0, %1}, %2;" : "=f"(f.x), "=f"(f.y) : "l"(v)); return f;
}
// pack two floats -> fp16x2 (first arg low half), as uint32
__device__ __forceinline__ uint32_t pkhf2(float lo, float hi) {
    uint32_t r;
    asm("{ .reg .f16 l, h; cvt.rn.f16.f32 l, %1; cvt.rn.f16.f32 h, %2; mov.b32 %0, {l, h}; }"
        : "=r"(r) : "f"(lo), "f"(hi));
    return r;
}
// unpack fp16x2 -> two floats
__device__ __forceinline__ float2 uphf2(uint32_t v) {
    float2 f;
    asm("{ .reg .f16 l, h; mov.b32 {l, h}, %2; cvt.f32.f16 %0, l; cvt.f32.f16 %1, h; }"
        : "=f"(f.x), "=f"(f.y) : "r"(v));
    return f;
}
__device__ __forceinline__ void mma_fp16(float* c, uint32_t a0, uint32_t a1,
                                         uint32_t a2, uint32_t a3,
                                         uint32_t b0, uint32_t b1) {
    asm volatile(
        "mma.sync.aligned.m16n8k16.row.col.f32.f16.f16.f32 "
        "{%0,%1,%2,%3}, {%4,%5,%6,%7}, {%8,%9}, {%0,%1,%2,%3};"
        : "+f"(c[0]), "+f"(c[1]), "+f"(c[2]), "+f"(c[3])
        : "r"(a0), "r"(a1), "r"(a2), "r"(a3), "r"(b0), "r"(b1));
}

// =====================================================================
// Kernel A: Wh = h @ W ; 32 rows x 128 f per CTA, 256 threads.
// Epilogue: fp16 store WhT[b][f][j] + si/sj/uv computed from fp32 acc.
// =====================================================================
__global__ void __launch_bounds__(256) k_wh(const float* __restrict__ h,
                                            const float* __restrict__ W,
                                            const float* __restrict__ a) {
    const int b = blockIdx.y;
    const int i0 = blockIdx.x * 32;

    __shared__ float hsT[32][40];    // [k][r], padded
    __shared__ float Ws[32][128];    // [k][f]
    __shared__ float aS[256];

    const int tid = threadIdx.x;
    aS[tid] = a[tid];
    const int fgrp = tid & 31, rgrp = tid >> 5;
    const int rbase = rgrp * 4, fbase = fgrp * 4;

    unsigned long long acc[4][2];
#pragma unroll
    for (int r = 0; r < 4; r++) { acc[r][0] = 0ULL; acc[r][1] = 0ULL; }

    for (int k0 = 0; k0 < FF; k0 += 32) {
        __syncthreads();
        {   // h tile: 32 rows x 32 k (one float4 per thread), transposed store
            int r = tid >> 3, kq = tid & 7;
            float4 v = *(const float4*)(h + ((size_t)(b * NN + i0 + r)) * FF + k0 + kq * 4);
            hsT[kq * 4 + 0][r] = v.x;
            hsT[kq * 4 + 1][r] = v.y;
            hsT[kq * 4 + 2][r] = v.z;
            hsT[kq * 4 + 3][r] = v.w;
        }
#pragma unroll
        for (int q = 0; q < 4; q++) {   // W chunk: 32 k x 128 f
            int idx = tid + 256 * q;
            int kk = idx >> 5, fq = idx & 31;
            *(float4*)&Ws[kk][fq * 4] = *(const float4*)(W + (size_t)(k0 + kk) * FF + fq * 4);
        }
        __syncthreads();

#pragma unroll 8
        for (int kk = 0; kk < 32; kk++) {
            float4 hr = *(float4*)&hsT[kk][rbase];
            float4 wf = *(float4*)&Ws[kk][fbase];
            unsigned long long w01 = pack2(wf.x, wf.y);
            unsigned long long w23 = pack2(wf.z, wf.w);
            float hv[4] = {hr.x, hr.y, hr.z, hr.w};
#pragma unroll
            for (int r = 0; r < 4; r++) {
                unsigned long long hb = bcast2(hv[r]);
                fma2(acc[r][0], hb, w01);
                fma2(acc[r][1], hb, w23);
            }
        }
    }

    float va[4][4];
#pragma unroll
    for (int r = 0; r < 4; r++) {
        float2 t0 = unpack2(acc[r][0]);
        float2 t1 = unpack2(acc[r][1]);
        va[r][0] = t0.x; va[r][1] = t0.y; va[r][2] = t1.x; va[r][3] = t1.y;
    }

    // fp16 store transposed: [b][f][j]
#pragma unroll
    for (int f = 0; f < 4; f++) {
        uint32_t h01 = pkhf2(va[0][f], va[1][f]);
        uint32_t h23 = pkhf2(va[2][f], va[3][f]);
        size_t idx = ((size_t)(b * FF) + fbase + f) * NN + i0 + rbase;  // fp16 elements
        *(uint2*)((__half*)g_Wh + idx) = make_uint2(h01, h23);
    }

    // si/sj from fp32 accumulators: warp reduce over fgrp (f dimension)
    float psi[4], psj[4];
#pragma unroll
    for (int r = 0; r < 4; r++) {
        float si = 0.f, sj = 0.f;
#pragma unroll
        for (int f = 0; f < 4; f++) {
            si += va[r][f] * aS[fbase + f];
            sj += va[r][f] * aS[FF + fbase + f];
        }
#pragma unroll
        for (int o = 16; o; o >>= 1) {
            si += __shfl_xor_sync(0xFFFFFFFFu, si, o);
            sj += __shfl_xor_sync(0xFFFFFFFFu, sj, o);
        }
        psi[r] = si; psj[r] = sj;
    }
    if (fgrp == 0) {
#pragma unroll
        for (int r = 0; r < 4; r++) {
            int row = b * NN + i0 + rbase + r;
            g_si[row] = psi[r];
            g_uv[row] = make_float2(__expf(psj[r]), __expf(0.2f * psj[r]));
        }
    }
}

// =====================================================================
// Kernel C: fused masked-softmax + P @ Wh via mma.sync fp16 (2-term) + ELU
// A = P split fp16 hi/lo (~22 bits); B = Wh single fp16.
// CTA = 128 i-rows x 128 f, 8 warps, j tiles of 16, double-buffered B.
// =====================================================================
__global__ void __launch_bounds__(256, 1) k_attn(const int* __restrict__ adj,
                                                 float* __restrict__ out) {
    __shared__ float2 uvS[NN];          // 32 KB
    __shared__ uint4  stg4[512];        // 8 KB: 2 stages x 128 f x 32B
    char* stg = (char*)stg4;

    const int tid = threadIdx.x;
    const int lane = tid & 31, w = tid >> 5;
    const int c = lane & 3, fq = lane >> 2;
    const int b = blockIdx.y;
    const int i0 = blockIdx.x * 128;

#pragma unroll
    for (int k = 0; k < 16; k++) {
        int idx = tid + 256 * k;
        uvS[idx] = g_uv[b * NN + idx];
    }

    const int r0 = i0 + w * 16 + fq;
    const int r1 = r0 + 8;
    const float si0 = g_si[b * NN + r0];
    const float si1 = g_si[b * NN + r1];
    const float c10 = __expf(si0), c20 = __expf(0.2f * si0), th0 = __expf(-si0);
    const float c11 = __expf(si1), c21 = __expf(0.2f * si1), th1 = __expf(-si1);

    const int2* a00 = (const int2*)(adj + ((size_t)(b * NN + r0)) * NN + 2 * c);
    const int2* a10 = (const int2*)(adj + ((size_t)(b * NN + r1)) * NN + 2 * c);

    // staging role: thread -> (f row, 16B half), chunk-swizzled
    const int f = tid >> 1;
    const int hh = tid & 1;
    const uint4* src = g_Wh + (size_t)(b * FF + f) * (NN / 8);   // 512 uint4 per row
    char* dst0 = stg + f * 32 + 16 * (hh ^ ((f >> 2) & 1));

    // consumer B addressing (nt-independent chunk swizzle)
    const int sfl = (fq >> 2) & 1;
    const int off0 = 16 * sfl + 4 * c;
    const int off1 = 16 * (sfl ^ 1) + 4 * c;
    const char* bb = stg + fq * 32;
    const float2* uvp = uvS + 2 * c;

    float acc[16][4];
#pragma unroll
    for (int nt = 0; nt < 16; nt++)
#pragma unroll
        for (int k = 0; k < 4; k++) acc[nt][k] = 0.f;
    float z0 = 0.f, z1 = 0.f;

    // prologue prefetch
    uint4 cb = src[hh];
    int2 A00 = __ldcs(a00), A01 = __ldcs(a00 + 4);
    int2 A10 = __ldcs(a10), A11 = __ldcs(a10 + 4);

    auto compute = [&](int tc) {
        const int J = tc * 16;
        float4 uvA = *(const float4*)(uvp + J);
        float4 uvB = *(const float4*)(uvp + J + 8);
        float p00 = A00.x > 0 ? (uvA.x > th0 ? c10 * uvA.x : c20 * uvA.y) : 0.f;
        float p01 = A00.y > 0 ? (uvA.z > th0 ? c10 * uvA.z : c20 * uvA.w) : 0.f;
        float p08 = A01.x > 0 ? (uvB.x > th0 ? c10 * uvB.x : c20 * uvB.y) : 0.f;
        float p09 = A01.y > 0 ? (uvB.z > th0 ? c10 * uvB.z : c20 * uvB.w) : 0.f;
        float p10 = A10.x > 0 ? (uvA.x > th1 ? c11 * uvA.x : c21 * uvA.y) : 0.f;
        float p11 = A10.y > 0 ? (uvA.z > th1 ? c11 * uvA.z : c21 * uvA.w) : 0.f;
        float p18 = A11.x > 0 ? (uvB.x > th1 ? c11 * uvB.x : c21 * uvB.y) : 0.f;
        float p19 = A11.y > 0 ? (uvB.z > th1 ? c11 * uvB.z : c21 * uvB.w) : 0.f;
        z0 += (p00 + p01) + (p08 + p09);
        z1 += (p10 + p11) + (p18 + p19);

        if (tc + 1 < NIT) {
            int o = (tc + 1) * 8;
            A00 = __ldcs(a00 + o); A01 = __ldcs(a00 + o + 4);
            A10 = __ldcs(a10 + o); A11 = __ldcs(a10 + o + 4);
        }

        // fp16 hi/lo split -> A fragments
        uint32_t ah0 = pkhf2(p00, p01), ah1 = pkhf2(p10, p11);
        uint32_t ah2 = pkhf2(p08, p09), ah3 = pkhf2(p18, p19);
        float2 f0 = uphf2(ah0), f1 = uphf2(ah1), f2 = uphf2(ah2), f3 = uphf2(ah3);
        uint32_t al0 = pkhf2(p00 - f0.x, p01 - f0.y);
        uint32_t al1 = pkhf2(p10 - f1.x, p11 - f1.y);
        uint32_t al2 = pkhf2(p08 - f2.x, p09 - f2.y);
        uint32_t al3 = pkhf2(p18 - f3.x, p19 - f3.y);

        const char* sbb = bb + (tc & 1) * 4096;
#pragma unroll
        for (int nt = 0; nt < 16; nt++) {
            const char* pb = sbb + nt * 256;
            uint32_t b0 = *(const uint32_t*)(pb + off0);
            uint32_t b1 = *(const uint32_t*)(pb + off1);
            mma_fp16(acc[nt], ah0, ah1, ah2, ah3, b0, b1);
            mma_fp16(acc[nt], al0, al1, al2, al3, b0, b1);
        }
    };

#pragma unroll 1
    for (int t = 0; t < NIT; t++) {
        __syncthreads();
        // stage tile t (chunk 2t+hh of row f) into buf t&1
        *(uint4*)(dst0 + (t & 1) * 4096) = cb;
        if (t + 1 < NIT) cb = src[2 * (t + 1) + hh];
        if (t > 0) compute(t - 1);
    }
    __syncthreads();
    compute(NIT - 1);

    // Z reduction over the 4 lanes sharing a row
    z0 += __shfl_xor_sync(0xFFFFFFFFu, z0, 1);
    z0 += __shfl_xor_sync(0xFFFFFFFFu, z0, 2);
    z1 += __shfl_xor_sync(0xFFFFFFFFu, z1, 1);
    z1 += __shfl_xor_sync(0xFFFFFFFFu, z1, 2);
    const float iz0 = 1.0f / z0;
    const float iz1 = 1.0f / z1;

    float* o0 = out + ((size_t)(b * NN + r0)) * FF + 2 * c;
    float* o1 = out + ((size_t)(b * NN + r1)) * FF + 2 * c;
#pragma unroll
    for (int nt = 0; nt < 16; nt++) {
        float x0 = acc[nt][0] * iz0, x1 = acc[nt][1] * iz0;
        float y0 = acc[nt][2] * iz1, y1 = acc[nt][3] * iz1;
        x0 = x0 > 0.f ? x0 : (__expf(x0) - 1.0f);
        x1 = x1 > 0.f ? x1 : (__expf(x1) - 1.0f);
        y0 = y0 > 0.f ? y0 : (__expf(y0) - 1.0f);
        y1 = y1 > 0.f ? y1 : (__expf(y1) - 1.0f);
        *(float2*)(o0 + nt * 8) = make_float2(x0, x1);
        *(float2*)(o1 + nt * 8) = make_float2(y0, y1);
    }
}

// =====================================================================
extern "C" void kernel_launch(void* const* d_in, const int* in_sizes, int n_in,
                              void* d_out, int out_size) {
    const float* h   = (const float*)d_in[0];
    const int*   adj = (const int*)d_in[1];
    const float* W   = (const float*)d_in[2];
    const float* a   = (const float*)d_in[3];
    float* out = (float*)d_out;

    k_wh<<<dim3(NN / 32, BB), 256>>>(h, W, a);
    k_attn<<<dim3(NN / 128, BB), 256>>>(adj, out);
}

// round 8
// speedup vs baseline: 1.9005x; 1.0031x over previous
#include <cuda_runtime.h>
#include <cuda_fp16.h>
#include <cstdint>

#define BB 4
#define NN 4096
#define FF 128
#define NIT 256           // 4096 / 16 j-tiles

// ---------------- scratch (no allocations allowed) ----------------
__device__ uint4  g_Wh[(size_t)BB * FF * NN / 8];    // WhT fp16 [b][f][j], 4MB
__device__ float  g_si[BB * NN];
__device__ float2 g_uv[BB * NN];                     // {e^{sj}, e^{0.2 sj}}

// ---------------- helpers ----------------
__device__ __forceinline__ unsigned long long pack2(float lo, float hi) {
    unsigned long long r; asm("mov.b64 %0, {%1, %2};" : "=l"(r) : "f"(lo), "f"(hi)); return r;
}
__device__ __forceinline__ unsigned long long bcast2(float v) {
    unsigned long long r; asm("mov.b64 %0, {%1, %1};" : "=l"(r) : "f"(v)); return r;
}
__device__ __forceinline__ void fma2(unsigned long long& d, unsigned long long a, unsigned long long b) {
    asm("fma.rn.f32x2 %0, %1, %2, %0;" : "+l"(d) : "l"(a), "l"(b));
}
__device__ __forceinline__ float2 unpack2(unsigned long long v) {
    float2 f; asm("mov.b64 {%0, %1}, %2;" : "=f"(f.x), "=f"(f.y) : "l"(v)); return f;
}
// pack two floats -> fp16x2 (first arg low half), as uint32
__device__ __forceinline__ uint32_t pkhf2(float lo, float hi) {
    uint32_t r;
    asm("{ .reg .f16 l, h; cvt.rn.f16.f32 l, %1; cvt.rn.f16.f32 h, %2; mov.b32 %0, {l, h}; }"
        : "=r"(r) : "f"(lo), "f"(hi));
    return r;
}
// unpack fp16x2 -> two floats
__device__ __forceinline__ float2 uphf2(uint32_t v) {
    float2 f;
    asm("{ .reg .f16 l, h; mov.b32 {l, h}, %2; cvt.f32.f16 %0, l; cvt.f32.f16 %1, h; }"
        : "=f"(f.x), "=f"(f.y) : "r"(v));
    return f;
}
__device__ __forceinline__ void mma_fp16(float* c, uint32_t a0, uint32_t a1,
                                         uint32_t a2, uint32_t a3,
                                         uint32_t b0, uint32_t b1) {
    asm volatile(
        "mma.sync.aligned.m16n8k16.row.col.f32.f16.f16.f32 "
        "{%0,%1,%2,%3}, {%4,%5,%6,%7}, {%8,%9}, {%0,%1,%2,%3};"
        : "+f"(c[0]), "+f"(c[1]), "+f"(c[2]), "+f"(c[3])
        : "r"(a0), "r"(a1), "r"(a2), "r"(a3), "r"(b0), "r"(b1));
}

// =====================================================================
// Kernel A: Wh = h @ W ; 32 rows x 128 f per CTA, 256 threads.
// Epilogue: fp16 store WhT[b][f][j] + si/sj/uv computed from fp32 acc.
// =====================================================================
__global__ void __launch_bounds__(256) k_wh(const float* __restrict__ h,
                                            const float* __restrict__ W,
                                            const float* __restrict__ a) {
    const int b = blockIdx.y;
    const int i0 = blockIdx.x * 32;

    __shared__ float hsT[32][40];    // [k][r], padded
    __shared__ float Ws[32][128];    // [k][f]
    __shared__ float aS[256];

    const int tid = threadIdx.x;
    aS[tid] = a[tid];
    const int fgrp = tid & 31, rgrp = tid >> 5;
    const int rbase = rgrp * 4, fbase = fgrp * 4;

    unsigned long long acc[4][2];
#pragma unroll
    for (int r = 0; r < 4; r++) { acc[r][0] = 0ULL; acc[r][1] = 0ULL; }

    for (int k0 = 0; k0 < FF; k0 += 32) {
        __syncthreads();
        {   // h tile: 32 rows x 32 k (one float4 per thread), transposed store
            int r = tid >> 3, kq = tid & 7;
            float4 v = *(const float4*)(h + ((size_t)(b * NN + i0 + r)) * FF + k0 + kq * 4);
            hsT[kq * 4 + 0][r] = v.x;
            hsT[kq * 4 + 1][r] = v.y;
            hsT[kq * 4 + 2][r] = v.z;
            hsT[kq * 4 + 3][r] = v.w;
        }
#pragma unroll
        for (int q = 0; q < 4; q++) {   // W chunk: 32 k x 128 f
            int idx = tid + 256 * q;
            int kk = idx >> 5, fq = idx & 31;
            *(float4*)&Ws[kk][fq * 4] = *(const float4*)(W + (size_t)(k0 + kk) * FF + fq * 4);
        }
        __syncthreads();

#pragma unroll 8
        for (int kk = 0; kk < 32; kk++) {
            float4 hr = *(float4*)&hsT[kk][rbase];
            float4 wf = *(float4*)&Ws[kk][fbase];
            unsigned long long w01 = pack2(wf.x, wf.y);
            unsigned long long w23 = pack2(wf.z, wf.w);
            float hv[4] = {hr.x, hr.y, hr.z, hr.w};
#pragma unroll
            for (int r = 0; r < 4; r++) {
                unsigned long long hb = bcast2(hv[r]);
                fma2(acc[r][0], hb, w01);
                fma2(acc[r][1], hb, w23);
            }
        }
    }

    float va[4][4];
#pragma unroll
    for (int r = 0; r < 4; r++) {
        float2 t0 = unpack2(acc[r][0]);
        float2 t1 = unpack2(acc[r][1]);
        va[r][0] = t0.x; va[r][1] = t0.y; va[r][2] = t1.x; va[r][3] = t1.y;
    }

    // fp16 store transposed: [b][f][j]
#pragma unroll
    for (int f = 0; f < 4; f++) {
        uint32_t h01 = pkhf2(va[0][f], va[1][f]);
        uint32_t h23 = pkhf2(va[2][f], va[3][f]);
        size_t idx = ((size_t)(b * FF) + fbase + f) * NN + i0 + rbase;  // fp16 elements
        *(uint2*)((__half*)g_Wh + idx) = make_uint2(h01, h23);
    }

    // si/sj from fp32 accumulators: warp reduce over fgrp (f dimension)
    float psi[4], psj[4];
#pragma unroll
    for (int r = 0; r < 4; r++) {
        float si = 0.f, sj = 0.f;
#pragma unroll
        for (int f = 0; f < 4; f++) {
            si += va[r][f] * aS[fbase + f];
            sj += va[r][f] * aS[FF + fbase + f];
        }
#pragma unroll
        for (int o = 16; o; o >>= 1) {
            si += __shfl_xor_sync(0xFFFFFFFFu, si, o);
            sj += __shfl_xor_sync(0xFFFFFFFFu, sj, o);
        }
        psi[r] = si; psj[r] = sj;
    }
    if (fgrp == 0) {
#pragma unroll
        for (int r = 0; r < 4; r++) {
            int row = b * NN + i0 + rbase + r;
            g_si[row] = psi[r];
            g_uv[row] = make_float2(__expf(psj[r]), __expf(0.2f * psj[r]));
        }
    }
}

// =====================================================================
// Kernel C: fused masked-softmax + P @ Wh via mma.sync fp16 (2-term) + ELU
// mma burst reordered into blocks of 8 independent accumulators:
// batch B-loads -> 8 hi-mmas -> 8 lo-mmas (no RAW bubbles).
// =====================================================================
__global__ void __launch_bounds__(256, 1) k_attn(const int* __restrict__ adj,
                                                 float* __restrict__ out) {
    __shared__ float2 uvS[NN];          // 32 KB
    __shared__ uint4  stg4[512];        // 8 KB: 2 stages x 128 f x 32B
    char* stg = (char*)stg4;

    const int tid = threadIdx.x;
    const int lane = tid & 31, w = tid >> 5;
    const int c = lane & 3, fq = lane >> 2;
    const int b = blockIdx.y;
    const int i0 = blockIdx.x * 128;

#pragma unroll
    for (int k = 0; k < 16; k++) {
        int idx = tid + 256 * k;
        uvS[idx] = g_uv[b * NN + idx];
    }

    const int r0 = i0 + w * 16 + fq;
    const int r1 = r0 + 8;
    const float si0 = g_si[b * NN + r0];
    const float si1 = g_si[b * NN + r1];
    const float c10 = __expf(si0), c20 = __expf(0.2f * si0), th0 = __expf(-si0);
    const float c11 = __expf(si1), c21 = __expf(0.2f * si1), th1 = __expf(-si1);

    const int2* a00 = (const int2*)(adj + ((size_t)(b * NN + r0)) * NN + 2 * c);
    const int2* a10 = (const int2*)(adj + ((size_t)(b * NN + r1)) * NN + 2 * c);

    // staging role: thread -> (f row, 16B half), chunk-swizzled
    const int f = tid >> 1;
    const int hh = tid & 1;
    const uint4* src = g_Wh + (size_t)(b * FF + f) * (NN / 8);   // 512 uint4 per row
    char* dst0 = stg + f * 32 + 16 * (hh ^ ((f >> 2) & 1));

    // consumer B addressing (nt-independent chunk swizzle)
    const int sfl = (fq >> 2) & 1;
    const int off0 = 16 * sfl + 4 * c;
    const int off1 = 16 * (sfl ^ 1) + 4 * c;
    const char* bb = stg + fq * 32;
    const float2* uvp = uvS + 2 * c;

    float acc[16][4];
#pragma unroll
    for (int nt = 0; nt < 16; nt++)
#pragma unroll
        for (int k = 0; k < 4; k++) acc[nt][k] = 0.f;
    float z0 = 0.f, z1 = 0.f;

    // prologue prefetch
    uint4 cb = src[hh];
    int2 A00 = __ldcs(a00), A01 = __ldcs(a00 + 4);
    int2 A10 = __ldcs(a10), A11 = __ldcs(a10 + 4);

    auto compute = [&](int tc) {
        const int J = tc * 16;
        float4 uvA = *(const float4*)(uvp + J);
        float4 uvB = *(const float4*)(uvp + J + 8);
        float p00 = A00.x > 0 ? (uvA.x > th0 ? c10 * uvA.x : c20 * uvA.y) : 0.f;
        float p01 = A00.y > 0 ? (uvA.z > th0 ? c10 * uvA.z : c20 * uvA.w) : 0.f;
        float p08 = A01.x > 0 ? (uvB.x > th0 ? c10 * uvB.x : c20 * uvB.y) : 0.f;
        float p09 = A01.y > 0 ? (uvB.z > th0 ? c10 * uvB.z : c20 * uvB.w) : 0.f;
        float p10 = A10.x > 0 ? (uvA.x > th1 ? c11 * uvA.x : c21 * uvA.y) : 0.f;
        float p11 = A10.y > 0 ? (uvA.z > th1 ? c11 * uvA.z : c21 * uvA.w) : 0.f;
        float p18 = A11.x > 0 ? (uvB.x > th1 ? c11 * uvB.x : c21 * uvB.y) : 0.f;
        float p19 = A11.y > 0 ? (uvB.z > th1 ? c11 * uvB.z : c21 * uvB.w) : 0.f;
        z0 += (p00 + p01) + (p08 + p09);
        z1 += (p10 + p11) + (p18 + p19);

        if (tc + 1 < NIT) {
            int o = (tc + 1) * 8;
            A00 = __ldcs(a00 + o); A01 = __ldcs(a00 + o + 4);
            A10 = __ldcs(a10 + o); A11 = __ldcs(a10 + o + 4);
        }

        // fp16 hi/lo split -> A fragments
        uint32_t ah0 = pkhf2(p00, p01), ah1 = pkhf2(p10, p11);
        uint32_t ah2 = pkhf2(p08, p09), ah3 = pkhf2(p18, p19);
        float2 f0 = uphf2(ah0), f1 = uphf2(ah1), f2 = uphf2(ah2), f3 = uphf2(ah3);
        uint32_t al0 = pkhf2(p00 - f0.x, p01 - f0.y);
        uint32_t al1 = pkhf2(p10 - f1.x, p11 - f1.y);
        uint32_t al2 = pkhf2(p08 - f2.x, p09 - f2.y);
        uint32_t al3 = pkhf2(p18 - f3.x, p19 - f3.y);

        const char* sbb = bb + (tc & 1) * 4096;
#pragma unroll
        for (int blk = 0; blk < 2; blk++) {
            const char* pb = sbb + blk * (8 * 256);
            uint32_t bv[16];
#pragma unroll
            for (int nt = 0; nt < 8; nt++) {
                bv[2 * nt]     = *(const uint32_t*)(pb + nt * 256 + off0);
                bv[2 * nt + 1] = *(const uint32_t*)(pb + nt * 256 + off1);
            }
#pragma unroll
            for (int nt = 0; nt < 8; nt++)
                mma_fp16(acc[blk * 8 + nt], ah0, ah1, ah2, ah3, bv[2 * nt], bv[2 * nt + 1]);
#pragma unroll
            for (int nt = 0; nt < 8; nt++)
                mma_fp16(acc[blk * 8 + nt], al0, al1, al2, al3, bv[2 * nt], bv[2 * nt + 1]);
        }
    };

#pragma unroll 1
    for (int t = 0; t < NIT; t++) {
        __syncthreads();
        // stage tile t (chunk 2t+hh of row f) into buf t&1
        *(uint4*)(dst0 + (t & 1) * 4096) = cb;
        if (t + 1 < NIT) cb = src[2 * (t + 1) + hh];
        if (t > 0) compute(t - 1);
    }
    __syncthreads();
    compute(NIT - 1);

    // Z reduction over the 4 lanes sharing a row
    z0 += __shfl_xor_sync(0xFFFFFFFFu, z0, 1);
    z0 += __shfl_xor_sync(0xFFFFFFFFu, z0, 2);
    z1 += __shfl_xor_sync(0xFFFFFFFFu, z1, 1);
    z1 += __shfl_xor_sync(0xFFFFFFFFu, z1, 2);
    const float iz0 = 1.0f / z0;
    const float iz1 = 1.0f / z1;

    float* o0 = out + ((size_t)(b * NN + r0)) * FF + 2 * c;
    float* o1 = out + ((size_t)(b * NN + r1)) * FF + 2 * c;
#pragma unroll
    for (int nt = 0; nt < 16; nt++) {
        float x0 = acc[nt][0] * iz0, x1 = acc[nt][1] * iz0;
        float y0 = acc[nt][2] * iz1, y1 = acc[nt][3] * iz1;
        x0 = x0 > 0.f ? x0 : (__expf(x0) - 1.0f);
        x1 = x1 > 0.f ? x1 : (__expf(x1) - 1.0f);
        y0 = y0 > 0.f ? y0 : (__expf(y0) - 1.0f);
        y1 = y1 > 0.f ? y1 : (__expf(y1) - 1.0f);
        *(float2*)(o0 + nt * 8) = make_float2(x0, x1);
        *(float2*)(o1 + nt * 8) = make_float2(y0, y1);
    }
}

// =====================================================================
extern "C" void kernel_launch(void* const* d_in, const int* in_sizes, int n_in,
                              void* d_out, int out_size) {
    const float* h   = (const float*)d_in[0];
    const int*   adj = (const int*)d_in[1];
    const float* W   = (const float*)d_in[2];
    const float* a   = (const float*)d_in[3];
    float* out = (float*)d_out;

    k_wh<<<dim3(NN / 32, BB), 256>>>(h, W, a);
    k_attn<<<dim3(NN / 128, BB), 256>>>(adj, out);
}